// round 1
// baseline (speedup 1.0000x reference)
#include <cuda_runtime.h>
#include <math.h>

#define LL   8
#define NN   16384
#define KC   16
#define DD   256
#define D4   (4*DD)    // 1024
#define D3   (3*DD)    // 768

// ---------------- scratch (device globals; no allocation allowed) ----------
__device__ float g_Wx  [NN * D4];  // 64 MB : x @ W_w + b for current level
__device__ float g_Hu  [NN * DD];  // 16 MB : h_prev @ U_f
__device__ float g_hsum[NN * DD];  // 16 MB
__device__ float g_f   [NN * DD];  // 16 MB
__device__ float g_iuo [NN * D3];  // 48 MB

// ---------------- generic f32 GEMM: C[M,N] = A[M,K] @ B[K,N] (+bias) -------
// Tile 64x64, BK=16, 256 threads, 4x4 per thread. M,N multiples of 64, K of 16.
__global__ __launch_bounds__(256)
void gemm_kernel(const float* __restrict__ A, const float* __restrict__ B,
                 const float* __restrict__ bias, float* __restrict__ C,
                 int M, int N, int K)
{
    __shared__ float As[16][64];   // transposed: As[k][m]
    __shared__ float Bs[16][64];   // Bs[k][n]

    const int tid = threadIdx.x;
    const int tx  = tid & 15;      // n-group
    const int ty  = tid >> 4;      // m-group
    const int bm  = blockIdx.y * 64;
    const int bn  = blockIdx.x * 64;

    // A-load mapping: each thread loads one float4 (row = tid/4, k-chunk = tid%4)
    const int arow = tid >> 2;
    const int akc  = (tid & 3) * 4;
    // B-load mapping: row = tid/16, col4 = (tid%16)*4
    const int brow = tid >> 4;
    const int bcol = (tid & 15) * 4;

    float acc[4][4];
#pragma unroll
    for (int i = 0; i < 4; i++)
#pragma unroll
        for (int j = 0; j < 4; j++) acc[i][j] = 0.f;

    for (int k0 = 0; k0 < K; k0 += 16) {
        // load A tile (64 x 16), store transposed
        float4 av = *reinterpret_cast<const float4*>(&A[(size_t)(bm + arow) * K + k0 + akc]);
        As[akc + 0][arow] = av.x;
        As[akc + 1][arow] = av.y;
        As[akc + 2][arow] = av.z;
        As[akc + 3][arow] = av.w;
        // load B tile (16 x 64)
        *reinterpret_cast<float4*>(&Bs[brow][bcol]) =
            *reinterpret_cast<const float4*>(&B[(size_t)(k0 + brow) * N + bn + bcol]);
        __syncthreads();

#pragma unroll
        for (int k = 0; k < 16; k++) {
            float4 a = *reinterpret_cast<const float4*>(&As[k][ty * 4]);
            float4 b = *reinterpret_cast<const float4*>(&Bs[k][tx * 4]);
            float ar[4] = {a.x, a.y, a.z, a.w};
            float br[4] = {b.x, b.y, b.z, b.w};
#pragma unroll
            for (int i = 0; i < 4; i++)
#pragma unroll
                for (int j = 0; j < 4; j++) acc[i][j] += ar[i] * br[j];
        }
        __syncthreads();
    }

    float bv[4] = {0.f, 0.f, 0.f, 0.f};
    if (bias) {
#pragma unroll
        for (int j = 0; j < 4; j++) bv[j] = bias[bn + tx * 4 + j];
    }
#pragma unroll
    for (int i = 0; i < 4; i++) {
        float* crow = &C[(size_t)(bm + ty * 4 + i) * N + bn + tx * 4];
        float4 o;
        o.x = acc[i][0] + bv[0];
        o.y = acc[i][1] + bv[1];
        o.z = acc[i][2] + bv[2];
        o.w = acc[i][3] + bv[3];
        *reinterpret_cast<float4*>(crow) = o;
    }
}

// ---------------- gather + child reduction ---------------------------------
// One block per node, 256 threads (= D dims).
// hsum[n,d] = sum_k valid h_prev[idx-1, d]
// f   [n,d] = sum_k valid sigmoid(Wf[n,d] + Hu[idx-1, d]) * c_prev[idx-1, d]
// idx <= 0 contributes 0 (idx==-1 masked; idx==0 gathers the zero row).
__global__ __launch_bounds__(256)
void gather_kernel(const int* __restrict__ idx,
                   const float* __restrict__ h_prev,   // may be null (level 0)
                   const float* __restrict__ c_prev,
                   const float* __restrict__ Hu,
                   const float* __restrict__ Wx,
                   float* __restrict__ hsum, float* __restrict__ f)
{
    const int n = blockIdx.x;
    const int d = threadIdx.x;

    __shared__ int sidx[KC];
    if (d < KC) sidx[d] = idx[n * KC + d];
    __syncthreads();

    float hs = 0.f, fs = 0.f;
    if (h_prev) {
        const float wf = Wx[(size_t)n * D4 + d];
#pragma unroll
        for (int k = 0; k < KC; k++) {
            int j = sidx[k];
            if (j >= 1) {
                size_t r = (size_t)(j - 1) * DD + d;
                hs += h_prev[r];
                float z  = wf + Hu[r];
                float g  = 1.f / (1.f + expf(-z));
                fs += g * c_prev[r];
            }
        }
    }
    hsum[(size_t)n * DD + d] = hs;
    f   [(size_t)n * DD + d] = fs;
}

// ---------------- gates + state update -------------------------------------
__global__ __launch_bounds__(256)
void gates_kernel(const float* __restrict__ iuo, const float* __restrict__ Wx,
                  const float* __restrict__ f,
                  float* __restrict__ out_h, float* __restrict__ out_c)
{
    const int t = blockIdx.x * blockDim.x + threadIdx.x;  // n*D + d
    const int n = t >> 8;
    const int d = t & 255;

    const float* iu = &iuo[(size_t)n * D3];
    const float* wx = &Wx [(size_t)n * D4];

    float i_ = 1.f / (1.f + expf(-(iu[d]          + wx[DD     + d])));
    float u_ = tanhf(        iu[DD + d]           + wx[2 * DD + d]);
    float o_ = 1.f / (1.f + expf(-(iu[2 * DD + d] + wx[3 * DD + d])));

    float nc = i_ * u_ + f[t];
    out_c[t] = nc;
    out_h[t] = o_ * tanhf(nc);
}

// ---------------- launch ----------------------------------------------------
extern "C" void kernel_launch(void* const* d_in, const int* in_sizes, int n_in,
                              void* d_out, int out_size)
{
    const float* tensor  = (const float*)d_in[0];  // [L, N, 256]
    const int*   indices = (const int*)  d_in[1];  // [L, N, 16]
    const float* W_w     = (const float*)d_in[2];  // [256, 1024]
    const float* W_b     = (const float*)d_in[3];  // [1024]
    const float* U_f     = (const float*)d_in[4];  // [256, 256]
    const float* U_iuo   = (const float*)d_in[5];  // [256, 768]

    float* out_h = (float*)d_out;                  // [L, N, 256]
    float* out_c = out_h + (size_t)LL * NN * DD;   // [L, N, 256]

    float* wx;   cudaGetSymbolAddress((void**)&wx,   g_Wx);
    float* hu;   cudaGetSymbolAddress((void**)&hu,   g_Hu);
    float* hsum; cudaGetSymbolAddress((void**)&hsum, g_hsum);
    float* fbuf; cudaGetSymbolAddress((void**)&fbuf, g_f);
    float* iuo;  cudaGetSymbolAddress((void**)&iuo,  g_iuo);

    const dim3 blk(256);
    const dim3 gWx (D4 / 64, NN / 64);   // (16, 256)
    const dim3 gHu (DD / 64, NN / 64);   // (4, 256)
    const dim3 gIuo(D3 / 64, NN / 64);   // (12, 256)

    for (int l = 0; l < LL; l++) {
        const float* x   = tensor  + (size_t)l * NN * DD;
        const int*   idx = indices + (size_t)l * NN * KC;
        const float* hp  = (l == 0) ? nullptr : out_h + (size_t)(l - 1) * NN * DD;
        const float* cp  = (l == 0) ? nullptr : out_c + (size_t)(l - 1) * NN * DD;

        // Wx = x @ W_w + b     [N, 1024]
        gemm_kernel<<<gWx, blk>>>(x, W_w, W_b, wx, NN, D4, DD);

        // Hu = h_prev @ U_f    [N, 256]   (skip at level 0 — gather writes zeros)
        if (l > 0)
            gemm_kernel<<<gHu, blk>>>(hp, U_f, nullptr, hu, NN, DD, DD);

        // child gather + reduce
        gather_kernel<<<NN, blk>>>(idx, hp, cp, hu, wx, hsum, fbuf);

        // iuo = hsum @ U_iuo   [N, 768]
        gemm_kernel<<<gIuo, blk>>>(hsum, U_iuo, nullptr, iuo, NN, D3, DD);

        // gates + state update, write h/c for this level
        gates_kernel<<<(NN * DD) / 256, blk>>>(iuo, wx, fbuf,
                                               out_h + (size_t)l * NN * DD,
                                               out_c + (size_t)l * NN * DD);
    }
}

// round 3
// speedup vs baseline: 1.6774x; 1.6774x over previous
#include <cuda_runtime.h>
#include <cuda_bf16.h>
#include <cstdint>
#include <math.h>

#define LL   8
#define NN   16384
#define KC   16
#define DD   256
#define D4   (4*DD)    // 1024
#define D3   (3*DD)    // 768

#define SWZ128(o) ((o) ^ (((o) >> 3) & 0x70))

__device__ __forceinline__ uint32_t smem_u32(const void* p) {
    uint32_t a;
    asm("{ .reg .u64 t; cvta.to.shared.u64 t, %1; cvt.u32.u64 %0, t; }" : "=r"(a) : "l"(p));
    return a;
}
__device__ __forceinline__ void ldsm_x4(uint32_t& r0, uint32_t& r1, uint32_t& r2,
                                        uint32_t& r3, uint32_t addr) {
    asm volatile("ldmatrix.sync.aligned.m8n8.x4.shared.b16 {%0,%1,%2,%3}, [%4];"
                 : "=r"(r0), "=r"(r1), "=r"(r2), "=r"(r3) : "r"(addr));
}
__device__ __forceinline__ void mma16816(float* c, const uint32_t* a, const uint32_t* b) {
    asm volatile("mma.sync.aligned.m16n8k16.row.col.f32.bf16.bf16.f32 "
                 "{%0,%1,%2,%3}, {%4,%5,%6,%7}, {%8,%9}, {%0,%1,%2,%3};"
                 : "+f"(c[0]), "+f"(c[1]), "+f"(c[2]), "+f"(c[3])
                 : "r"(a[0]), "r"(a[1]), "r"(a[2]), "r"(a[3]), "r"(b[0]), "r"(b[1]));
}

// ---------------- scratch (device globals) ---------------------------------
__device__ float g_Wx  [NN * D4];
__device__ float g_Hu  [NN * DD];
__device__ float g_hsum[NN * DD];
__device__ float g_f   [NN * DD];
__device__ float g_iuo [NN * D3];
// preprocessed weights: 64 tiles of [128 n][64 k] bf16, SW128-swizzled, 16KB each
// W_w: tiles 0..31  (8 n-tiles x 4 kc), U_f: 32..39 (2x4), U_iuo: 40..63 (6x4)
__device__ __align__(1024) unsigned char g_Bhi[64 * 16384];
__device__ __align__(1024) unsigned char g_Blo[64 * 16384];

// ---------------- weight preprocessing -------------------------------------
// W: [256(k), Ncw(n)] f32 row-major -> hi/lo bf16 tiles, K-major, swizzled.
__global__ __launch_bounds__(256)
void prep_kernel(const float* __restrict__ W, int Ncw, int tile_base)
{
    int idx = blockIdx.x * blockDim.x + threadIdx.x;
    if (idx >= Ncw * 256) return;
    int n = idx % Ncw, k = idx / Ncw;
    float v = W[idx];
    __nv_bfloat16 hi = __float2bfloat16(v);
    __nv_bfloat16 lo = __float2bfloat16(v - __bfloat162float(hi));
    unsigned tile = (unsigned)(tile_base + (n >> 7) * 4 + (k >> 6));
    unsigned off  = tile * 16384u + SWZ128((unsigned)((n & 127) * 128 + (k & 63) * 2));
    *(__nv_bfloat16*)(g_Bhi + off) = hi;
    *(__nv_bfloat16*)(g_Blo + off) = lo;
}

// ---------------- HMMA GEMM: C[M,Nc] = A[M,256] @ W + bias -----------------
// CTA: 128(M) x 128(N), 8 warps (4m x 2n), warp tile 32x64.
// K in 4 chunks of 64; each resident chunk used by 3 hi/lo passes.
__global__ __launch_bounds__(256, 2)
void gemm_mma(const float* __restrict__ A, int tbase,
              const float* __restrict__ bias, float* __restrict__ C, int Nc)
{
    extern __shared__ char smem[];      // [Ahi 16K][Alo 16K][Bhi 16K][Blo 16K]
    const uint32_t sb = smem_u32(smem);
    const int tid = threadIdx.x, wid = tid >> 5, lane = tid & 31;
    const int wm = wid & 3, wn = wid >> 2;
    const int bm = blockIdx.y * 128, bn = blockIdx.x * 128;

    float acc[2][8][4];
#pragma unroll
    for (int i = 0; i < 2; i++)
#pragma unroll
        for (int j = 0; j < 8; j++)
#pragma unroll
            for (int q = 0; q < 4; q++) acc[i][j][q] = 0.f;

    // ldmatrix lane address components
    const int a_row16 = (lane & 7) + ((lane >> 3) & 1) * 8;
    const int a_kb    = (lane >> 4) * 16;
    const int b_row16 = (lane & 7) + ((lane >> 4) << 3);
    const int b_kb    = ((lane >> 3) & 1) * 16;

    uint32_t aRow[2], aXor[2], bRow[4], bXor[4];
#pragma unroll
    for (int mt = 0; mt < 2; mt++) {
        uint32_t r = (uint32_t)(wm * 32 + mt * 16 + a_row16) * 128u;
        aRow[mt] = r; aXor[mt] = (r >> 3) & 0x70;
    }
#pragma unroll
    for (int np = 0; np < 4; np++) {
        uint32_t r = (uint32_t)(wn * 64 + np * 16 + b_row16) * 128u;
        bRow[np] = r; bXor[np] = (r >> 3) & 0x70;
    }

    for (int kc = 0; kc < 4; kc++) {
        // ---- A chunk [128 x 64] f32 -> bf16 hi/lo, swizzled ----
#pragma unroll
        for (int i = 0; i < 8; i++) {
            int e   = tid + i * 256;          // 2048 float4 slots
            int row = e >> 4, c4 = e & 15;
            float4 v = *(const float4*)&A[(size_t)(bm + row) * 256 + kc * 64 + c4 * 4];
            __nv_bfloat162 h0, h1, l0, l1;
            h0.x = __float2bfloat16(v.x); h0.y = __float2bfloat16(v.y);
            h1.x = __float2bfloat16(v.z); h1.y = __float2bfloat16(v.w);
            l0.x = __float2bfloat16(v.x - __bfloat162float(h0.x));
            l0.y = __float2bfloat16(v.y - __bfloat162float(h0.y));
            l1.x = __float2bfloat16(v.z - __bfloat162float(h1.x));
            l1.y = __float2bfloat16(v.w - __bfloat162float(h1.y));
            uint32_t off = SWZ128((uint32_t)(row * 128 + c4 * 8));
            uint2 hh, ll;
            hh.x = *(uint32_t*)&h0; hh.y = *(uint32_t*)&h1;
            ll.x = *(uint32_t*)&l0; ll.y = *(uint32_t*)&l1;
            *(uint2*)(smem + off)         = hh;
            *(uint2*)(smem + 16384 + off) = ll;
        }
        // ---- B chunk tiles (already bf16 + swizzled) ----
        {
            const uint4* gh = (const uint4*)(g_Bhi + (size_t)(tbase + blockIdx.x * 4 + kc) * 16384);
            const uint4* gl = (const uint4*)(g_Blo + (size_t)(tbase + blockIdx.x * 4 + kc) * 16384);
            uint4* sh = (uint4*)(smem + 32768);
            uint4* sl = (uint4*)(smem + 49152);
#pragma unroll
            for (int i = 0; i < 4; i++) {
                sh[tid + i * 256] = gh[tid + i * 256];
                sl[tid + i * 256] = gl[tid + i * 256];
            }
        }
        __syncthreads();

        // ---- 3 hi/lo passes over the resident chunk ----
#pragma unroll
        for (int pass = 0; pass < 3; pass++) {
            const uint32_t sA = sb + (pass == 2 ? 16384u : 0u);
            const uint32_t sB = sb + 32768u + (pass == 1 ? 16384u : 0u);
#pragma unroll
            for (int ks = 0; ks < 4; ks++) {
                uint32_t av[2][4], bv[4][4];
#pragma unroll
                for (int mt = 0; mt < 2; mt++)
                    ldsm_x4(av[mt][0], av[mt][1], av[mt][2], av[mt][3],
                            sA + aRow[mt] + (((uint32_t)(ks * 32 + a_kb)) ^ aXor[mt]));
#pragma unroll
                for (int np = 0; np < 4; np++)
                    ldsm_x4(bv[np][0], bv[np][1], bv[np][2], bv[np][3],
                            sB + bRow[np] + (((uint32_t)(ks * 32 + b_kb)) ^ bXor[np]));
#pragma unroll
                for (int mt = 0; mt < 2; mt++)
#pragma unroll
                    for (int nt = 0; nt < 8; nt++)
                        mma16816(acc[mt][nt], av[mt], &bv[nt >> 1][(nt & 1) * 2]);
            }
        }
        __syncthreads();
    }

    // ---- epilogue ----
    const int r0 = lane >> 2, c0 = (lane & 3) * 2;
#pragma unroll
    for (int mt = 0; mt < 2; mt++) {
#pragma unroll
        for (int nt = 0; nt < 8; nt++) {
            int row = bm + wm * 32 + mt * 16 + r0;
            int col = bn + wn * 64 + nt * 8 + c0;
            float b0 = 0.f, b1 = 0.f;
            if (bias) { b0 = bias[col]; b1 = bias[col + 1]; }
            float2 v0, v1;
            v0.x = acc[mt][nt][0] + b0; v0.y = acc[mt][nt][1] + b1;
            v1.x = acc[mt][nt][2] + b0; v1.y = acc[mt][nt][3] + b1;
            *(float2*)&C[(size_t)row * Nc + col]       = v0;
            *(float2*)&C[(size_t)(row + 8) * Nc + col] = v1;
        }
    }
}

// ---------------- gather + child reduction ---------------------------------
__global__ __launch_bounds__(256)
void gather_kernel(const int* __restrict__ idx,
                   const float* __restrict__ h_prev,
                   const float* __restrict__ c_prev,
                   const float* __restrict__ Hu,
                   const float* __restrict__ Wx,
                   float* __restrict__ hsum, float* __restrict__ f)
{
    const int n = blockIdx.x;
    const int d = threadIdx.x;

    __shared__ int sidx[KC];
    if (d < KC) sidx[d] = idx[n * KC + d];
    __syncthreads();

    float hs = 0.f, fs = 0.f;
    if (h_prev) {
        const float wf = Wx[(size_t)n * D4 + d];
#pragma unroll
        for (int k = 0; k < KC; k++) {
            int j = sidx[k];
            if (j >= 1) {
                size_t r = (size_t)(j - 1) * DD + d;
                hs += h_prev[r];
                float z = wf + Hu[r];
                float g = 1.f / (1.f + expf(-z));
                fs += g * c_prev[r];
            }
        }
    }
    hsum[(size_t)n * DD + d] = hs;
    f   [(size_t)n * DD + d] = fs;
}

// ---------------- gates + state update -------------------------------------
__global__ __launch_bounds__(256)
void gates_kernel(const float* __restrict__ iuo, const float* __restrict__ Wx,
                  const float* __restrict__ f,
                  float* __restrict__ out_h, float* __restrict__ out_c)
{
    const int t = blockIdx.x * blockDim.x + threadIdx.x;
    const int n = t >> 8;
    const int d = t & 255;

    const float* iu = &iuo[(size_t)n * D3];
    const float* wx = &Wx [(size_t)n * D4];

    float i_ = 1.f / (1.f + expf(-(iu[d]          + wx[DD     + d])));
    float u_ = tanhf(        iu[DD + d]           + wx[2 * DD + d]);
    float o_ = 1.f / (1.f + expf(-(iu[2 * DD + d] + wx[3 * DD + d])));

    float nc = i_ * u_ + f[t];
    out_c[t] = nc;
    out_h[t] = o_ * tanhf(nc);
}

// ---------------- launch ----------------------------------------------------
extern "C" void kernel_launch(void* const* d_in, const int* in_sizes, int n_in,
                              void* d_out, int out_size)
{
    const float* tensor  = (const float*)d_in[0];
    const int*   indices = (const int*)  d_in[1];
    const float* W_w     = (const float*)d_in[2];
    const float* W_b     = (const float*)d_in[3];
    const float* U_f     = (const float*)d_in[4];
    const float* U_iuo   = (const float*)d_in[5];

    float* out_h = (float*)d_out;
    float* out_c = out_h + (size_t)LL * NN * DD;

    float* wx;   cudaGetSymbolAddress((void**)&wx,   g_Wx);
    float* hu;   cudaGetSymbolAddress((void**)&hu,   g_Hu);
    float* hsum; cudaGetSymbolAddress((void**)&hsum, g_hsum);
    float* fbuf; cudaGetSymbolAddress((void**)&fbuf, g_f);
    float* iuo;  cudaGetSymbolAddress((void**)&iuo,  g_iuo);

    const int SMEM_DYN = 65536;
    cudaFuncSetAttribute(gemm_mma, cudaFuncAttributeMaxDynamicSharedMemorySize, SMEM_DYN);

    // one-time weight preprocessing (hi/lo bf16, transposed + swizzled tiles)
    prep_kernel<<<(1024 * 256) / 256, 256>>>(W_w,   1024, 0);
    prep_kernel<<<( 256 * 256) / 256, 256>>>(U_f,    256, 32);
    prep_kernel<<<( 768 * 256) / 256, 256>>>(U_iuo,  768, 40);

    const dim3 blk(256);
    for (int l = 0; l < LL; l++) {
        const float* x   = tensor  + (size_t)l * NN * DD;
        const int*   idx = indices + (size_t)l * NN * KC;
        const float* hp  = (l == 0) ? nullptr : out_h + (size_t)(l - 1) * NN * DD;
        const float* cp  = (l == 0) ? nullptr : out_c + (size_t)(l - 1) * NN * DD;

        // Wx = x @ W_w + b   [N, 1024]
        gemm_mma<<<dim3(8, 128), blk, SMEM_DYN>>>(x, 0, W_b, wx, D4);

        // Hu = h_prev @ U_f  [N, 256]
        if (l > 0)
            gemm_mma<<<dim3(2, 128), blk, SMEM_DYN>>>(hp, 32, nullptr, hu, DD);

        // child gather + reduce
        gather_kernel<<<NN, blk>>>(idx, hp, cp, hu, wx, hsum, fbuf);

        // iuo = hsum @ U_iuo [N, 768]
        gemm_mma<<<dim3(6, 128), blk, SMEM_DYN>>>(hsum, 40, nullptr, iuo, D3);

        // gates + state update
        gates_kernel<<<(NN * DD) / 256, blk>>>(iuo, wx, fbuf,
                                               out_h + (size_t)l * NN * DD,
                                               out_c + (size_t)l * NN * DD);
    }
}

// round 4
// speedup vs baseline: 2.0016x; 1.1932x over previous
#include <cuda_runtime.h>
#include <cuda_bf16.h>
#include <cstdint>
#include <math.h>

#define LL   8
#define NN   16384
#define KC   16
#define DD   256
#define D4   (4*DD)
#define D3   (3*DD)
#define NTOT (LL*NN)            // 131072

#define SWZ128(o) ((o) ^ (((o) >> 3) & 0x70))
#define TILE_B 16384            // one 128x64 bf16 tile

__device__ __forceinline__ uint32_t smem_u32(const void* p) {
    uint32_t a;
    asm("{ .reg .u64 t; cvta.to.shared.u64 t, %1; cvt.u32.u64 %0, t; }" : "=r"(a) : "l"(p));
    return a;
}
__device__ __forceinline__ void ldsm_x4(uint32_t& r0, uint32_t& r1, uint32_t& r2,
                                        uint32_t& r3, uint32_t addr) {
    asm volatile("ldmatrix.sync.aligned.m8n8.x4.shared.b16 {%0,%1,%2,%3}, [%4];"
                 : "=r"(r0), "=r"(r1), "=r"(r2), "=r"(r3) : "r"(addr));
}
__device__ __forceinline__ void mma16816(float* c, const uint32_t* a, const uint32_t* b) {
    asm volatile("mma.sync.aligned.m16n8k16.row.col.f32.bf16.bf16.f32 "
                 "{%0,%1,%2,%3}, {%4,%5,%6,%7}, {%8,%9}, {%0,%1,%2,%3};"
                 : "+f"(c[0]), "+f"(c[1]), "+f"(c[2]), "+f"(c[3])
                 : "r"(a[0]), "r"(a[1]), "r"(a[2]), "r"(a[3]), "r"(b[0]), "r"(b[1]));
}
#define CP_ASYNC16(dst, src) \
    asm volatile("cp.async.cg.shared.global [%0], [%1], 16;" :: "r"(dst), "l"(src))
#define CP_COMMIT asm volatile("cp.async.commit_group;" ::: "memory")
#define CP_WAIT1  asm volatile("cp.async.wait_group 1;" ::: "memory")
#define CP_WAIT0  asm volatile("cp.async.wait_group 0;" ::: "memory")

// ---------------- scratch (device globals) ---------------------------------
__device__ float g_Wf  [NTOT * DD];   // 128 MB : x @ W_f + b_f, all levels
__device__ float g_Hu  [NN * DD];
__device__ float g_f   [NN * DD];
__device__ float g_iuo [NN * D3];
// A operands, bf16 hi/lo, tile-swizzled [128x64 per tile]
__device__ __align__(1024) unsigned char g_Axhi[NTOT/128 * 4 * TILE_B]; // 64 MB
__device__ __align__(1024) unsigned char g_Axlo[NTOT/128 * 4 * TILE_B];
__device__ __align__(1024) unsigned char g_Ahshi[NN/128 * 4 * TILE_B];  // 8 MB
__device__ __align__(1024) unsigned char g_Ahslo[NN/128 * 4 * TILE_B];
__device__ __align__(1024) unsigned char g_Ahhi [NN/128 * 4 * TILE_B];
__device__ __align__(1024) unsigned char g_Ahlo [NN/128 * 4 * TILE_B];
// B tiles: Wf: 0..7 (2nb x 4kc) | U_f: 8..15 (2x4) | B_ext: 16..63 (6nb x 8kc)
__device__ __align__(1024) unsigned char g_Bhi[64 * TILE_B];
__device__ __align__(1024) unsigned char g_Blo[64 * TILE_B];

// ---------------- weight prep ----------------------------------------------
__device__ __forceinline__ void put_b(unsigned tile, int n_loc, int k_loc, float v) {
    __nv_bfloat16 hi = __float2bfloat16(v);
    __nv_bfloat16 lo = __float2bfloat16(v - __bfloat162float(hi));
    unsigned off = tile * TILE_B + SWZ128((unsigned)(n_loc * 128 + k_loc * 2));
    *(__nv_bfloat16*)(g_Bhi + off) = hi;
    *(__nv_bfloat16*)(g_Blo + off) = lo;
}
// Wf part of W_w: B_f[k][n] = W_w[k*1024 + n], n<256. tiles 0..7
// U_f: tiles 8..15
__global__ __launch_bounds__(256)
void prep_small(const float* __restrict__ W_w, const float* __restrict__ U_f)
{
    int idx = blockIdx.x * blockDim.x + threadIdx.x;   // 256*256 each
    int n = idx & 255, k = idx >> 8;
    put_b(0 + (n >> 7) * 4 + (k >> 6), n & 127, k & 63, W_w[k * 1024 + n]);
    put_b(8 + (n >> 7) * 4 + (k >> 6), n & 127, k & 63, U_f[k * 256 + n]);
}
// B_ext [512k x 768n]: k<256 -> U_iuo[k][n]; k>=256 -> W_w[k-256][256+n]. tiles 16..63
__global__ __launch_bounds__(256)
void prep_ext(const float* __restrict__ W_w, const float* __restrict__ U_iuo)
{
    int idx = blockIdx.x * blockDim.x + threadIdx.x;   // 512*768
    if (idx >= 512 * 768) return;
    int n = idx % 768, k = idx / 768;
    float v = (k < 256) ? U_iuo[k * 768 + n] : W_w[(k - 256) * 1024 + 256 + n];
    put_b(16 + (n >> 7) * 8 + (k >> 6), n & 127, k & 63, v);
}

// ---------------- x -> bf16 hi/lo tiles (all levels, once) ------------------
__global__ __launch_bounds__(256)
void xconv_kernel(const float* __restrict__ x)
{
    int t = blockIdx.x * blockDim.x + threadIdx.x;     // NTOT*64 float4 slots
    int n = t >> 6, c4 = t & 63;
    float4 v = *(const float4*)&x[(size_t)t * 4];
    __nv_bfloat162 h0, h1, l0, l1;
    h0.x = __float2bfloat16(v.x); h0.y = __float2bfloat16(v.y);
    h1.x = __float2bfloat16(v.z); h1.y = __float2bfloat16(v.w);
    l0.x = __float2bfloat16(v.x - __bfloat162float(h0.x));
    l0.y = __float2bfloat16(v.y - __bfloat162float(h0.y));
    l1.x = __float2bfloat16(v.z - __bfloat162float(h1.x));
    l1.y = __float2bfloat16(v.w - __bfloat162float(h1.y));
    size_t tile = (size_t)(n >> 7) * 4 + (c4 >> 4);
    unsigned off = SWZ128((unsigned)((n & 127) * 128 + (c4 & 15) * 8));
    uint2 hh, ll;
    hh.x = *(uint32_t*)&h0; hh.y = *(uint32_t*)&h1;
    ll.x = *(uint32_t*)&l0; ll.y = *(uint32_t*)&l1;
    *(uint2*)(g_Axhi + tile * TILE_B + off) = hh;
    *(uint2*)(g_Axlo + tile * TILE_B + off) = ll;
}

// ---------------- pipelined HMMA GEMM ---------------------------------------
// C[M,Nc] = A[M, 64*kchunks] @ B + bias.  A given as tiled hi/lo buffers:
// chunks 0..3 from A0, chunks 4..7 from A1. B tile = btile_base + bx*kchunks + kc.
__global__ __launch_bounds__(256, 1)
void gemm_mma(const unsigned char* __restrict__ A0h, const unsigned char* __restrict__ A0l,
              const unsigned char* __restrict__ A1h, const unsigned char* __restrict__ A1l,
              int kchunks, int btile_base,
              const float* __restrict__ bias, float* __restrict__ C, int Nc)
{
    extern __shared__ char smem[];   // 2 stages x [Ahi|Alo|Bhi|Blo] x 16KB
    const uint32_t sb = smem_u32(smem);
    const int tid = threadIdx.x, wid = tid >> 5, lane = tid & 31;
    const int wm = wid & 3, wn = wid >> 2;
    const int mb = blockIdx.y, bn = blockIdx.x * 128;

    float acc[2][8][4];
#pragma unroll
    for (int i = 0; i < 2; i++)
#pragma unroll
        for (int j = 0; j < 8; j++)
#pragma unroll
            for (int q = 0; q < 4; q++) acc[i][j][q] = 0.f;

    const int a_row16 = (lane & 7) + ((lane >> 3) & 1) * 8;
    const int a_kb    = (lane >> 4) * 16;
    const int b_row16 = (lane & 7) + ((lane >> 4) << 3);
    const int b_kb    = ((lane >> 3) & 1) * 16;
    uint32_t aRow[2], aXor[2], bRow[4], bXor[4];
#pragma unroll
    for (int mt = 0; mt < 2; mt++) {
        uint32_t r = (uint32_t)(wm * 32 + mt * 16 + a_row16) * 128u;
        aRow[mt] = r; aXor[mt] = (r >> 3) & 0x70;
    }
#pragma unroll
    for (int np = 0; np < 4; np++) {
        uint32_t r = (uint32_t)(wn * 64 + np * 16 + b_row16) * 128u;
        bRow[np] = r; bXor[np] = (r >> 3) & 0x70;
    }

    // stage loader
    auto load_stage = [&](int stg, int kc) {
        const unsigned char* ah; const unsigned char* al;
        if (kc < 4) {
            size_t t = ((size_t)mb * 4 + kc) * TILE_B;
            ah = A0h + t; al = A0l + t;
        } else {
            size_t t = ((size_t)mb * 4 + (kc - 4)) * TILE_B;
            ah = A1h + t; al = A1l + t;
        }
        size_t bt = (size_t)(btile_base + blockIdx.x * kchunks + kc) * TILE_B;
        const unsigned char* srcs[4] = { ah, al, g_Bhi + bt, g_Blo + bt };
        uint32_t base = sb + (uint32_t)stg * 65536u;
#pragma unroll
        for (int j = 0; j < 4; j++) {
            uint32_t d = base + j * TILE_B + tid * 16;
            const unsigned char* s = srcs[j] + tid * 16;
#pragma unroll
            for (int i = 0; i < 4; i++)
                CP_ASYNC16(d + i * 4096, s + i * 4096);
        }
        CP_COMMIT;
    };

    load_stage(0, 0);

    for (int kc = 0; kc < kchunks; kc++) {
        if (kc + 1 < kchunks) { load_stage((kc + 1) & 1, kc + 1); CP_WAIT1; }
        else                  { CP_WAIT0; }
        __syncthreads();

        const uint32_t stg = sb + (uint32_t)(kc & 1) * 65536u;
#pragma unroll
        for (int pass = 0; pass < 3; pass++) {
            const uint32_t sA = stg + (pass == 2 ? TILE_B : 0u);
            const uint32_t sB = stg + 2u * TILE_B + (pass == 1 ? TILE_B : 0u);
#pragma unroll
            for (int ks = 0; ks < 4; ks++) {
                uint32_t av[2][4], bv[4][4];
#pragma unroll
                for (int mt = 0; mt < 2; mt++)
                    ldsm_x4(av[mt][0], av[mt][1], av[mt][2], av[mt][3],
                            sA + aRow[mt] + (((uint32_t)(ks * 32 + a_kb)) ^ aXor[mt]));
#pragma unroll
                for (int np = 0; np < 4; np++)
                    ldsm_x4(bv[np][0], bv[np][1], bv[np][2], bv[np][3],
                            sB + bRow[np] + (((uint32_t)(ks * 32 + b_kb)) ^ bXor[np]));
#pragma unroll
                for (int mt = 0; mt < 2; mt++)
#pragma unroll
                    for (int nt = 0; nt < 8; nt++)
                        mma16816(acc[mt][nt], av[mt], &bv[nt >> 1][(nt & 1) * 2]);
            }
        }
        __syncthreads();
    }

    // epilogue
    const int r0 = lane >> 2, c0 = (lane & 3) * 2;
    const int bm = mb * 128;
#pragma unroll
    for (int mt = 0; mt < 2; mt++) {
#pragma unroll
        for (int nt = 0; nt < 8; nt++) {
            int row = bm + wm * 32 + mt * 16 + r0;
            int col = bn + wn * 64 + nt * 8 + c0;
            float b0 = 0.f, b1 = 0.f;
            if (bias) { b0 = bias[col]; b1 = bias[col + 1]; }
            float2 v0, v1;
            v0.x = acc[mt][nt][0] + b0; v0.y = acc[mt][nt][1] + b1;
            v1.x = acc[mt][nt][2] + b0; v1.y = acc[mt][nt][3] + b1;
            *(float2*)&C[(size_t)row * Nc + col]       = v0;
            *(float2*)&C[(size_t)(row + 8) * Nc + col] = v1;
        }
    }
}

// ---------------- gather: hsum (bf16 hi/lo tiles) + f -----------------------
__global__ __launch_bounds__(256)
void gather_kernel(const int* __restrict__ idx,
                   const float* __restrict__ h_prev,
                   const float* __restrict__ c_prev,
                   const float* __restrict__ Hu,
                   const float* __restrict__ Wf,     // [N,256] this level
                   float* __restrict__ f)
{
    const int n = blockIdx.x;
    const int d = threadIdx.x;

    __shared__ int sidx[KC];
    if (d < KC) sidx[d] = idx[n * KC + d];
    __syncthreads();

    float hs = 0.f, fs = 0.f;
    if (h_prev) {
        const float wf = Wf[(size_t)n * DD + d];
#pragma unroll
        for (int k = 0; k < KC; k++) {
            int j = sidx[k];
            if (j >= 1) {
                size_t r = (size_t)(j - 1) * DD + d;
                hs += h_prev[r];
                float z = wf + Hu[r];
                float g = 1.f / (1.f + expf(-z));
                fs += g * c_prev[r];
            }
        }
    }
    f[(size_t)n * DD + d] = fs;
    // write hsum as bf16 hi/lo into tiled layout
    __nv_bfloat16 hi = __float2bfloat16(hs);
    __nv_bfloat16 lo = __float2bfloat16(hs - __bfloat162float(hi));
    size_t tile = (size_t)(n >> 7) * 4 + (d >> 6);
    unsigned off = SWZ128((unsigned)((n & 127) * 128 + (d & 63) * 2));
    *(__nv_bfloat16*)(g_Ahshi + tile * TILE_B + off) = hi;
    *(__nv_bfloat16*)(g_Ahslo + tile * TILE_B + off) = lo;
}

// ---------------- gates + state update (+ h hi/lo tiles) --------------------
__global__ __launch_bounds__(256)
void gates_kernel(const float* __restrict__ iuo, const float* __restrict__ f,
                  float* __restrict__ out_h, float* __restrict__ out_c)
{
    const int t = blockIdx.x * blockDim.x + threadIdx.x;
    const int n = t >> 8;
    const int d = t & 255;

    const float* iu = &iuo[(size_t)n * D3];
    float i_ = 1.f / (1.f + expf(-iu[d]));
    float u_ = tanhf(iu[DD + d]);
    float o_ = 1.f / (1.f + expf(-iu[2 * DD + d]));

    float nc = i_ * u_ + f[t];
    float nh = o_ * tanhf(nc);
    out_c[t] = nc;
    out_h[t] = nh;

    __nv_bfloat16 hi = __float2bfloat16(nh);
    __nv_bfloat16 lo = __float2bfloat16(nh - __bfloat162float(hi));
    size_t tile = (size_t)(n >> 7) * 4 + (d >> 6);
    unsigned off = SWZ128((unsigned)((n & 127) * 128 + (d & 63) * 2));
    *(__nv_bfloat16*)(g_Ahhi + tile * TILE_B + off) = hi;
    *(__nv_bfloat16*)(g_Ahlo + tile * TILE_B + off) = lo;
}

// ---------------- launch -----------------------------------------------------
extern "C" void kernel_launch(void* const* d_in, const int* in_sizes, int n_in,
                              void* d_out, int out_size)
{
    const float* tensor  = (const float*)d_in[0];
    const int*   indices = (const int*)  d_in[1];
    const float* W_w     = (const float*)d_in[2];
    const float* W_b     = (const float*)d_in[3];
    const float* U_f     = (const float*)d_in[4];
    const float* U_iuo   = (const float*)d_in[5];

    float* out_h = (float*)d_out;
    float* out_c = out_h + (size_t)LL * NN * DD;

    float* wfb;  cudaGetSymbolAddress((void**)&wfb,  g_Wf);
    float* hu;   cudaGetSymbolAddress((void**)&hu,   g_Hu);
    float* fbuf; cudaGetSymbolAddress((void**)&fbuf, g_f);
    float* iuo;  cudaGetSymbolAddress((void**)&iuo,  g_iuo);
    unsigned char *axhi, *axlo, *ahshi, *ahslo, *ahhi, *ahlo;
    cudaGetSymbolAddress((void**)&axhi,  g_Axhi);
    cudaGetSymbolAddress((void**)&axlo,  g_Axlo);
    cudaGetSymbolAddress((void**)&ahshi, g_Ahshi);
    cudaGetSymbolAddress((void**)&ahslo, g_Ahslo);
    cudaGetSymbolAddress((void**)&ahhi,  g_Ahhi);
    cudaGetSymbolAddress((void**)&ahlo,  g_Ahlo);

    const int SMEM_DYN = 131072;
    cudaFuncSetAttribute(gemm_mma, cudaFuncAttributeMaxDynamicSharedMemorySize, SMEM_DYN);

    const dim3 blk(256);

    // one-time prep
    prep_small<<<(256 * 256) / 256, blk>>>(W_w, U_f);
    prep_ext<<<(512 * 768 + 255) / 256, blk>>>(W_w, U_iuo);
    xconv_kernel<<<(NTOT * 64) / 256, blk>>>(tensor);

    // batched Wf = x @ W_f + b_f for all levels  [131072, 256]
    gemm_mma<<<dim3(2, NTOT / 128), blk, SMEM_DYN>>>(
        axhi, axlo, axhi, axlo, 4, 0, W_b, wfb, DD);

    for (int l = 0; l < LL; l++) {
        const int*   idx = indices + (size_t)l * NN * KC;
        const float* hp  = (l == 0) ? nullptr : out_h + (size_t)(l - 1) * NN * DD;
        const float* cp  = (l == 0) ? nullptr : out_c + (size_t)(l - 1) * NN * DD;

        // Hu = h_prev @ U_f
        if (l > 0)
            gemm_mma<<<dim3(2, NN / 128), blk, SMEM_DYN>>>(
                ahhi, ahlo, ahhi, ahlo, 4, 8, nullptr, hu, DD);

        // gather: hsum tiles + f
        gather_kernel<<<NN, blk>>>(idx, hp, cp, hu,
                                   wfb + (size_t)l * NN * DD, fbuf);

        // iuo = [hsum | x_l] @ B_ext + b_iuo   (K = 512)
        gemm_mma<<<dim3(6, NN / 128), blk, SMEM_DYN>>>(
            ahshi, ahslo,
            axhi + (size_t)l * (NN / 128) * 4 * TILE_B,
            axlo + (size_t)l * (NN / 128) * 4 * TILE_B,
            8, 16, W_b + 256, iuo, D3);

        // gates
        gates_kernel<<<(NN * DD) / 256, blk>>>(iuo, fbuf,
                                               out_h + (size_t)l * NN * DD,
                                               out_c + (size_t)l * NN * DD);
    }
}

// round 5
// speedup vs baseline: 2.6460x; 1.3220x over previous
#include <cuda_runtime.h>
#include <cuda_bf16.h>
#include <cstdint>
#include <math.h>

#define LL   8
#define NN   16384
#define KC   16
#define DD   256
#define D4   (4*DD)
#define D3   (3*DD)
#define NTOT (LL*NN)            // 131072

#define SWZ128(o) ((o) ^ (((o) >> 3) & 0x70))
#define TILE_B 16384            // one 128x64 bf16 tile

__device__ __forceinline__ uint32_t smem_u32(const void* p) {
    uint32_t a;
    asm("{ .reg .u64 t; cvta.to.shared.u64 t, %1; cvt.u32.u64 %0, t; }" : "=r"(a) : "l"(p));
    return a;
}
__device__ __forceinline__ void ldsm_x4(uint32_t& r0, uint32_t& r1, uint32_t& r2,
                                        uint32_t& r3, uint32_t addr) {
    asm volatile("ldmatrix.sync.aligned.m8n8.x4.shared.b16 {%0,%1,%2,%3}, [%4];"
                 : "=r"(r0), "=r"(r1), "=r"(r2), "=r"(r3) : "r"(addr));
}
__device__ __forceinline__ void mma16816(float* c, const uint32_t* a, const uint32_t* b) {
    asm volatile("mma.sync.aligned.m16n8k16.row.col.f32.bf16.bf16.f32 "
                 "{%0,%1,%2,%3}, {%4,%5,%6,%7}, {%8,%9}, {%0,%1,%2,%3};"
                 : "+f"(c[0]), "+f"(c[1]), "+f"(c[2]), "+f"(c[3])
                 : "r"(a[0]), "r"(a[1]), "r"(a[2]), "r"(a[3]), "r"(b[0]), "r"(b[1]));
}
// sigmoid via single-MUFU tanh.approx: sigma(z) = 0.5*tanh(z/2) + 0.5
__device__ __forceinline__ float sigmoid_fast(float z) {
    float t;
    asm("tanh.approx.f32 %0, %1;" : "=f"(t) : "f"(0.5f * z));
    return fmaf(0.5f, t, 0.5f);
}
#define CP_ASYNC16(dst, src) \
    asm volatile("cp.async.cg.shared.global [%0], [%1], 16;" :: "r"(dst), "l"(src))
#define CP_COMMIT asm volatile("cp.async.commit_group;" ::: "memory")
#define CP_WAIT1  asm volatile("cp.async.wait_group 1;" ::: "memory")
#define CP_WAIT0  asm volatile("cp.async.wait_group 0;" ::: "memory")

// ---------------- scratch (device globals) ---------------------------------
__device__ float g_Wf  [NTOT * DD];   // x @ W_f + b_f, all levels
__device__ float g_Hu  [NN * DD];
__device__ float g_f   [NN * DD];
__device__ float g_iuo [NN * D3];
// A operands, bf16 hi/lo, tile-swizzled [128x64 per tile]
__device__ __align__(1024) unsigned char g_Axhi[NTOT/128 * 4 * TILE_B];
__device__ __align__(1024) unsigned char g_Axlo[NTOT/128 * 4 * TILE_B];
__device__ __align__(1024) unsigned char g_Ahshi[NN/128 * 4 * TILE_B];
__device__ __align__(1024) unsigned char g_Ahslo[NN/128 * 4 * TILE_B];
__device__ __align__(1024) unsigned char g_Ahhi [NN/128 * 4 * TILE_B];
__device__ __align__(1024) unsigned char g_Ahlo [NN/128 * 4 * TILE_B];
// B tiles: Wf: 0..7 | U_f: 8..15 | B_ext: 16..63
__device__ __align__(1024) unsigned char g_Bhi[64 * TILE_B];
__device__ __align__(1024) unsigned char g_Blo[64 * TILE_B];

// ---------------- weight prep ----------------------------------------------
__device__ __forceinline__ void put_b(unsigned tile, int n_loc, int k_loc, float v) {
    __nv_bfloat16 hi = __float2bfloat16(v);
    __nv_bfloat16 lo = __float2bfloat16(v - __bfloat162float(hi));
    unsigned off = tile * TILE_B + SWZ128((unsigned)(n_loc * 128 + k_loc * 2));
    *(__nv_bfloat16*)(g_Bhi + off) = hi;
    *(__nv_bfloat16*)(g_Blo + off) = lo;
}
__global__ __launch_bounds__(256)
void prep_small(const float* __restrict__ W_w, const float* __restrict__ U_f)
{
    int idx = blockIdx.x * blockDim.x + threadIdx.x;
    int n = idx & 255, k = idx >> 8;
    put_b(0 + (n >> 7) * 4 + (k >> 6), n & 127, k & 63, W_w[k * 1024 + n]);
    put_b(8 + (n >> 7) * 4 + (k >> 6), n & 127, k & 63, U_f[k * 256 + n]);
}
__global__ __launch_bounds__(256)
void prep_ext(const float* __restrict__ W_w, const float* __restrict__ U_iuo)
{
    int idx = blockIdx.x * blockDim.x + threadIdx.x;
    if (idx >= 512 * 768) return;
    int n = idx % 768, k = idx / 768;
    float v = (k < 256) ? U_iuo[k * 768 + n] : W_w[(k - 256) * 1024 + 256 + n];
    put_b(16 + (n >> 7) * 8 + (k >> 6), n & 127, k & 63, v);
}

// ---------------- x -> bf16 hi/lo tiles (all levels, once) ------------------
__global__ __launch_bounds__(256)
void xconv_kernel(const float* __restrict__ x)
{
    int t = blockIdx.x * blockDim.x + threadIdx.x;
    int n = t >> 6, c4 = t & 63;
    float4 v = *(const float4*)&x[(size_t)t * 4];
    __nv_bfloat162 h0, h1, l0, l1;
    h0.x = __float2bfloat16(v.x); h0.y = __float2bfloat16(v.y);
    h1.x = __float2bfloat16(v.z); h1.y = __float2bfloat16(v.w);
    l0.x = __float2bfloat16(v.x - __bfloat162float(h0.x));
    l0.y = __float2bfloat16(v.y - __bfloat162float(h0.y));
    l1.x = __float2bfloat16(v.z - __bfloat162float(h1.x));
    l1.y = __float2bfloat16(v.w - __bfloat162float(h1.y));
    size_t tile = (size_t)(n >> 7) * 4 + (c4 >> 4);
    unsigned off = SWZ128((unsigned)((n & 127) * 128 + (c4 & 15) * 8));
    uint2 hh, ll;
    hh.x = *(uint32_t*)&h0; hh.y = *(uint32_t*)&h1;
    ll.x = *(uint32_t*)&l0; ll.y = *(uint32_t*)&l1;
    *(uint2*)(g_Axhi + tile * TILE_B + off) = hh;
    *(uint2*)(g_Axlo + tile * TILE_B + off) = ll;
}

// ---------------- pipelined HMMA GEMM ---------------------------------------
__global__ __launch_bounds__(256, 1)
void gemm_mma(const unsigned char* __restrict__ A0h, const unsigned char* __restrict__ A0l,
              const unsigned char* __restrict__ A1h, const unsigned char* __restrict__ A1l,
              int kchunks, int btile_base,
              const float* __restrict__ bias, float* __restrict__ C, int Nc)
{
    extern __shared__ char smem[];   // 2 stages x [Ahi|Alo|Bhi|Blo] x 16KB
    const uint32_t sb = smem_u32(smem);
    const int tid = threadIdx.x, wid = tid >> 5, lane = tid & 31;
    const int wm = wid & 3, wn = wid >> 2;
    const int mb = blockIdx.y, bn = blockIdx.x * 128;

    float acc[2][8][4];
#pragma unroll
    for (int i = 0; i < 2; i++)
#pragma unroll
        for (int j = 0; j < 8; j++)
#pragma unroll
            for (int q = 0; q < 4; q++) acc[i][j][q] = 0.f;

    const int a_row16 = (lane & 7) + ((lane >> 3) & 1) * 8;
    const int a_kb    = (lane >> 4) * 16;
    const int b_row16 = (lane & 7) + ((lane >> 4) << 3);
    const int b_kb    = ((lane >> 3) & 1) * 16;
    uint32_t aRow[2], aXor[2], bRow[4], bXor[4];
#pragma unroll
    for (int mt = 0; mt < 2; mt++) {
        uint32_t r = (uint32_t)(wm * 32 + mt * 16 + a_row16) * 128u;
        aRow[mt] = r; aXor[mt] = (r >> 3) & 0x70;
    }
#pragma unroll
    for (int np = 0; np < 4; np++) {
        uint32_t r = (uint32_t)(wn * 64 + np * 16 + b_row16) * 128u;
        bRow[np] = r; bXor[np] = (r >> 3) & 0x70;
    }

    auto load_stage = [&](int stg, int kc) {
        const unsigned char* ah; const unsigned char* al;
        if (kc < 4) {
            size_t t = ((size_t)mb * 4 + kc) * TILE_B;
            ah = A0h + t; al = A0l + t;
        } else {
            size_t t = ((size_t)mb * 4 + (kc - 4)) * TILE_B;
            ah = A1h + t; al = A1l + t;
        }
        size_t bt = (size_t)(btile_base + blockIdx.x * kchunks + kc) * TILE_B;
        const unsigned char* srcs[4] = { ah, al, g_Bhi + bt, g_Blo + bt };
        uint32_t base = sb + (uint32_t)stg * 65536u;
#pragma unroll
        for (int j = 0; j < 4; j++) {
            uint32_t d = base + j * TILE_B + tid * 16;
            const unsigned char* s = srcs[j] + tid * 16;
#pragma unroll
            for (int i = 0; i < 4; i++)
                CP_ASYNC16(d + i * 4096, s + i * 4096);
        }
        CP_COMMIT;
    };

    load_stage(0, 0);

    uint32_t av[2][2][4], bv[2][4][4];

    for (int kc = 0; kc < kchunks; kc++) {
        if (kc + 1 < kchunks) { load_stage((kc + 1) & 1, kc + 1); CP_WAIT1; }
        else                  { CP_WAIT0; }
        __syncthreads();

        const uint32_t stg = sb + (uint32_t)(kc & 1) * 65536u;

        // fragment prefetch helper: step s in 0..11, pass = s>>2, ks = s&3
#define LDFRAG(buf, s) do {                                                     \
            const int _p = (s) >> 2, _k = (s) & 3;                              \
            const uint32_t _sA = stg + (_p == 2 ? (uint32_t)TILE_B : 0u);       \
            const uint32_t _sB = stg + 2u * TILE_B + (_p == 1 ? (uint32_t)TILE_B : 0u); \
            _Pragma("unroll")                                                   \
            for (int mt = 0; mt < 2; mt++)                                      \
                ldsm_x4(av[buf][mt][0], av[buf][mt][1], av[buf][mt][2], av[buf][mt][3], \
                        _sA + aRow[mt] + (((uint32_t)(_k * 32 + a_kb)) ^ aXor[mt])); \
            _Pragma("unroll")                                                   \
            for (int np = 0; np < 4; np++)                                      \
                ldsm_x4(bv[buf][np][0], bv[buf][np][1], bv[buf][np][2], bv[buf][np][3], \
                        _sB + bRow[np] + (((uint32_t)(_k * 32 + b_kb)) ^ bXor[np])); \
        } while (0)

        LDFRAG(0, 0);
#pragma unroll
        for (int s = 0; s < 12; s++) {
            if (s < 11) LDFRAG((s + 1) & 1, s + 1);
            const int cb = s & 1;
#pragma unroll
            for (int mt = 0; mt < 2; mt++)
#pragma unroll
                for (int nt = 0; nt < 8; nt++)
                    mma16816(acc[mt][nt], av[cb][mt], &bv[cb][nt >> 1][(nt & 1) * 2]);
        }
#undef LDFRAG
        __syncthreads();
    }

    // epilogue
    const int r0 = lane >> 2, c0 = (lane & 3) * 2;
    const int bm = mb * 128;
#pragma unroll
    for (int mt = 0; mt < 2; mt++) {
#pragma unroll
        for (int nt = 0; nt < 8; nt++) {
            int row = bm + wm * 32 + mt * 16 + r0;
            int col = bn + wn * 64 + nt * 8 + c0;
            float b0 = 0.f, b1 = 0.f;
            if (bias) { b0 = bias[col]; b1 = bias[col + 1]; }
            float2 v0, v1;
            v0.x = acc[mt][nt][0] + b0; v0.y = acc[mt][nt][1] + b1;
            v1.x = acc[mt][nt][2] + b0; v1.y = acc[mt][nt][3] + b1;
            *(float2*)&C[(size_t)row * Nc + col]       = v0;
            *(float2*)&C[(size_t)(row + 8) * Nc + col] = v1;
        }
    }
}

// ---------------- gather: 4 nodes/block, float4/thread ----------------------
__global__ __launch_bounds__(256)
void gather_kernel(const int* __restrict__ idx,
                   const float* __restrict__ h_prev,
                   const float* __restrict__ c_prev,
                   const float* __restrict__ Hu,
                   const float* __restrict__ Wf,
                   float* __restrict__ f)
{
    const int nb = blockIdx.x * 4;
    const int t  = threadIdx.x;
    const int ln = t >> 6;                 // local node 0..3
    const int n  = nb + ln;
    const int d4 = (t & 63) * 4;

    __shared__ int sidx[4][KC];
    if (t < 64) sidx[t >> 4][t & 15] = idx[(nb + (t >> 4)) * KC + (t & 15)];
    __syncthreads();

    float4 hs = {0.f, 0.f, 0.f, 0.f}, fs = {0.f, 0.f, 0.f, 0.f};
    if (h_prev) {
        const float4 wf = *(const float4*)&Wf[(size_t)n * DD + d4];
#pragma unroll
        for (int k = 0; k < KC; k++) {
            int j = sidx[ln][k];
            if (j >= 1) {
                size_t r = (size_t)(j - 1) * DD + d4;
                float4 h  = *(const float4*)&h_prev[r];
                float4 hu = *(const float4*)&Hu[r];
                float4 c  = *(const float4*)&c_prev[r];
                hs.x += h.x; hs.y += h.y; hs.z += h.z; hs.w += h.w;
                fs.x += sigmoid_fast(wf.x + hu.x) * c.x;
                fs.y += sigmoid_fast(wf.y + hu.y) * c.y;
                fs.z += sigmoid_fast(wf.z + hu.z) * c.z;
                fs.w += sigmoid_fast(wf.w + hu.w) * c.w;
            }
        }
    }
    *(float4*)&f[(size_t)n * DD + d4] = fs;

    // hsum -> bf16 hi/lo tiles (4 values = uint2 per buffer)
    __nv_bfloat162 h0, h1, l0, l1;
    h0.x = __float2bfloat16(hs.x); h0.y = __float2bfloat16(hs.y);
    h1.x = __float2bfloat16(hs.z); h1.y = __float2bfloat16(hs.w);
    l0.x = __float2bfloat16(hs.x - __bfloat162float(h0.x));
    l0.y = __float2bfloat16(hs.y - __bfloat162float(h0.y));
    l1.x = __float2bfloat16(hs.z - __bfloat162float(h1.x));
    l1.y = __float2bfloat16(hs.w - __bfloat162float(h1.y));
    size_t tile = (size_t)(n >> 7) * 4 + (d4 >> 6);
    unsigned off = SWZ128((unsigned)((n & 127) * 128 + (d4 & 63) * 2));
    uint2 hh, ll;
    hh.x = *(uint32_t*)&h0; hh.y = *(uint32_t*)&h1;
    ll.x = *(uint32_t*)&l0; ll.y = *(uint32_t*)&l1;
    *(uint2*)(g_Ahshi + tile * TILE_B + off) = hh;
    *(uint2*)(g_Ahslo + tile * TILE_B + off) = ll;
}

// ---------------- gates + state update (+ h hi/lo tiles) --------------------
__global__ __launch_bounds__(256)
void gates_kernel(const float* __restrict__ iuo, const float* __restrict__ f,
                  float* __restrict__ out_h, float* __restrict__ out_c)
{
    const int t = blockIdx.x * blockDim.x + threadIdx.x;
    const int n = t >> 8;
    const int d = t & 255;

    const float* iu = &iuo[(size_t)n * D3];
    float i_ = 1.f / (1.f + expf(-iu[d]));
    float u_ = tanhf(iu[DD + d]);
    float o_ = 1.f / (1.f + expf(-iu[2 * DD + d]));

    float nc = i_ * u_ + f[t];
    float nh = o_ * tanhf(nc);
    out_c[t] = nc;
    out_h[t] = nh;

    __nv_bfloat16 hi = __float2bfloat16(nh);
    __nv_bfloat16 lo = __float2bfloat16(nh - __bfloat162float(hi));
    size_t tile = (size_t)(n >> 7) * 4 + (d >> 6);
    unsigned off = SWZ128((unsigned)((n & 127) * 128 + (d & 63) * 2));
    *(__nv_bfloat16*)(g_Ahhi + tile * TILE_B + off) = hi;
    *(__nv_bfloat16*)(g_Ahlo + tile * TILE_B + off) = lo;
}

// ---------------- launch -----------------------------------------------------
extern "C" void kernel_launch(void* const* d_in, const int* in_sizes, int n_in,
                              void* d_out, int out_size)
{
    const float* tensor  = (const float*)d_in[0];
    const int*   indices = (const int*)  d_in[1];
    const float* W_w     = (const float*)d_in[2];
    const float* W_b     = (const float*)d_in[3];
    const float* U_f     = (const float*)d_in[4];
    const float* U_iuo   = (const float*)d_in[5];

    float* out_h = (float*)d_out;
    float* out_c = out_h + (size_t)LL * NN * DD;

    float* wfb;  cudaGetSymbolAddress((void**)&wfb,  g_Wf);
    float* hu;   cudaGetSymbolAddress((void**)&hu,   g_Hu);
    float* fbuf; cudaGetSymbolAddress((void**)&fbuf, g_f);
    float* iuo;  cudaGetSymbolAddress((void**)&iuo,  g_iuo);
    unsigned char *axhi, *axlo, *ahshi, *ahslo, *ahhi, *ahlo;
    cudaGetSymbolAddress((void**)&axhi,  g_Axhi);
    cudaGetSymbolAddress((void**)&axlo,  g_Axlo);
    cudaGetSymbolAddress((void**)&ahshi, g_Ahshi);
    cudaGetSymbolAddress((void**)&ahslo, g_Ahslo);
    cudaGetSymbolAddress((void**)&ahhi,  g_Ahhi);
    cudaGetSymbolAddress((void**)&ahlo,  g_Ahlo);

    const int SMEM_DYN = 131072;
    cudaFuncSetAttribute(gemm_mma, cudaFuncAttributeMaxDynamicSharedMemorySize, SMEM_DYN);

    const dim3 blk(256);

    // one-time prep
    prep_small<<<(256 * 256) / 256, blk>>>(W_w, U_f);
    prep_ext<<<(512 * 768 + 255) / 256, blk>>>(W_w, U_iuo);
    xconv_kernel<<<(NTOT * 64) / 256, blk>>>(tensor);

    // batched Wf = x @ W_f + b_f for all levels
    gemm_mma<<<dim3(2, NTOT / 128), blk, SMEM_DYN>>>(
        axhi, axlo, axhi, axlo, 4, 0, W_b, wfb, DD);

    for (int l = 0; l < LL; l++) {
        const int*   idx = indices + (size_t)l * NN * KC;
        const float* hp  = (l == 0) ? nullptr : out_h + (size_t)(l - 1) * NN * DD;
        const float* cp  = (l == 0) ? nullptr : out_c + (size_t)(l - 1) * NN * DD;

        if (l > 0)
            gemm_mma<<<dim3(2, NN / 128), blk, SMEM_DYN>>>(
                ahhi, ahlo, ahhi, ahlo, 4, 8, nullptr, hu, DD);

        gather_kernel<<<NN / 4, blk>>>(idx, hp, cp, hu,
                                       wfb + (size_t)l * NN * DD, fbuf);

        gemm_mma<<<dim3(6, NN / 128), blk, SMEM_DYN>>>(
            ahshi, ahslo,
            axhi + (size_t)l * (NN / 128) * 4 * TILE_B,
            axlo + (size_t)l * (NN / 128) * 4 * TILE_B,
            8, 16, W_b + 256, iuo, D3);

        gates_kernel<<<(NN * DD) / 256, blk>>>(iuo, fbuf,
                                               out_h + (size_t)l * NN * DD,
                                               out_c + (size_t)l * NN * DD);
    }
}